// round 1
// baseline (speedup 1.0000x reference)
#include <cuda_runtime.h>
#include <cstdint>

// Problem constants
#define BATCH   16384
#define NCLS    1000
#define NPAD    1024
#define KDIM    1024

// GEMM tiling
#define BM 128
#define BN 128
#define BK 32
#define NT 8                 // number of N tiles (8*128 = 1024 >= 1000)
#define SLD 36               // smem row stride in floats (32 + 4 pad -> conflict-free frags)

// ---------------------------------------------------------------------------
// Scratch (zero-initialized at module load; pad rows of g_ct stay zero forever)
// ---------------------------------------------------------------------------
__device__ float g_xt[(size_t)BATCH * KDIM];     // tf32-rounded x
__device__ float g_ct[(size_t)NPAD * KDIM];      // tf32-rounded centers, zero-padded rows 1000..1023
__device__ float g_c2[NPAD];                     // exact fp32 ||c_j||^2 (pad stays 0, never used)
__device__ float g_pos[BATCH];                   // e[b, label_b]
__device__ float g_minxc[(size_t)BATCH * NT];    // per-(row, n-tile) min of e excluding label
__device__ float g_mincc[(size_t)NPAD * NT];     // per-(center, n-tile) min excluding diagonal

__device__ __forceinline__ float tf32_rna(float f) {
    uint32_t u;
    asm("cvt.rna.tf32.f32 %0, %1;" : "=r"(u) : "f"(f));
    return __uint_as_float(u);
}

// ---------------------------------------------------------------------------
// Prep: round-to-nearest tf32 copies
// ---------------------------------------------------------------------------
__global__ void prep_x_kernel(const float* __restrict__ src, int n4) {
    int i = blockIdx.x * blockDim.x + threadIdx.x;
    if (i < n4) {
        float4 v = reinterpret_cast<const float4*>(src)[i];
        v.x = tf32_rna(v.x); v.y = tf32_rna(v.y);
        v.z = tf32_rna(v.z); v.w = tf32_rna(v.w);
        reinterpret_cast<float4*>(g_xt)[i] = v;
    }
}

__global__ void prep_c_kernel(const float* __restrict__ src, int n4) {
    int i = blockIdx.x * blockDim.x + threadIdx.x;
    if (i < n4) {
        float4 v = reinterpret_cast<const float4*>(src)[i];
        v.x = tf32_rna(v.x); v.y = tf32_rna(v.y);
        v.z = tf32_rna(v.z); v.w = tf32_rna(v.w);
        reinterpret_cast<float4*>(g_ct)[i] = v;
    }
}

// ---------------------------------------------------------------------------
// Exact fp32 squared norms of centers (one block per class)
// ---------------------------------------------------------------------------
__global__ void c2_kernel(const float* __restrict__ centers) {
    int j = blockIdx.x;
    const float* row = centers + (size_t)j * KDIM;
    float acc = 0.f;
    for (int k = threadIdx.x; k < KDIM; k += 256) {
        float v = row[k];
        acc += v * v;
    }
    __shared__ float s[256];
    s[threadIdx.x] = acc;
    __syncthreads();
    for (int off = 128; off > 0; off >>= 1) {
        if (threadIdx.x < off) s[threadIdx.x] += s[threadIdx.x + off];
        __syncthreads();
    }
    if (threadIdx.x == 0) g_c2[j] = s[0];
}

// ---------------------------------------------------------------------------
// GEMM + fused min epilogue.
// Computes dot[b,c] = A_row_b . C_row_c over K=1024, then e = 0.5*c2[c] - dot.
// SELF=false: A = g_xt (M=16384); excludes c == label[b], writes g_pos, g_minxc.
// SELF=true:  A = g_ct (M=1000 logical, padded); excludes c == b, writes g_mincc.
// ---------------------------------------------------------------------------
__device__ __forceinline__ void cp_tile(const float* gbase, float* sbase, int tid) {
#pragma unroll
    for (int i = 0; i < 4; i++) {
        int g = i * 256 + tid;          // 0..1023
        int r = g >> 3;                 // 0..127
        int c4 = (g & 7) * 4;           // 0,4,...,28
        uint32_t d = (uint32_t)__cvta_generic_to_shared(sbase + r * SLD + c4);
        const float* s = gbase + (size_t)r * KDIM + c4;
        asm volatile("cp.async.cg.shared.global [%0], [%1], 16;" :: "r"(d), "l"(s));
    }
}

template <bool SELF>
__global__ void __launch_bounds__(256)
gemm_min_kernel(const int* __restrict__ labels) {
    extern __shared__ float smem[];
    float* As  = smem;                      // 2 * 128 * 36
    float* Bs  = smem + 2 * BM * SLD;       // 2 * 128 * 36
    float* c2s = Bs + 2 * BN * SLD;         // 128
    float* red = c2s + 128;                 // 128 * 2
    int*   labs = (int*)(red + 256);        // 128

    const int tid  = threadIdx.x;
    const int warp = tid >> 5;
    const int lane = tid & 31;
    const int wm   = warp >> 1;   // 0..3  (M warps, 32 rows each)
    const int wn   = warp & 1;    // 0..1  (N warps, 64 cols each)
    const int bx   = blockIdx.x;  // n-tile 0..7
    const int m0   = blockIdx.y * BM;
    const int n0   = bx * BN;

    const float* A = SELF ? g_ct : g_xt;

    if (tid < 128) {
        c2s[tid] = g_c2[n0 + tid];
        if (!SELF) labs[tid] = labels[m0 + tid];
    }

    float acc[2][8][4];
#pragma unroll
    for (int mi = 0; mi < 2; mi++)
#pragma unroll
        for (int ni = 0; ni < 8; ni++)
#pragma unroll
            for (int r = 0; r < 4; r++) acc[mi][ni][r] = 0.f;

    const float* Abase = A + (size_t)m0 * KDIM;
    const float* Bbase = g_ct + (size_t)n0 * KDIM;

    // prologue: stage 0
    cp_tile(Abase, As, tid);
    cp_tile(Bbase, Bs, tid);
    asm volatile("cp.async.commit_group;");

    const int KT = KDIM / BK;   // 32
    const int lr = lane >> 2, lc = lane & 3;

    for (int kt = 0; kt < KT; kt++) {
        if (kt + 1 < KT) {
            int st = (kt + 1) & 1;
            cp_tile(Abase + (kt + 1) * BK, As + st * BM * SLD, tid);
            cp_tile(Bbase + (kt + 1) * BK, Bs + st * BN * SLD, tid);
            asm volatile("cp.async.commit_group;");
            asm volatile("cp.async.wait_group 1;");
        } else {
            asm volatile("cp.async.wait_group 0;");
        }
        __syncthreads();

        const uint32_t* a_s = (const uint32_t*)(As + (kt & 1) * BM * SLD);
        const uint32_t* b_s = (const uint32_t*)(Bs + (kt & 1) * BN * SLD);

#pragma unroll
        for (int kk = 0; kk < 4; kk++) {
            uint32_t af[2][4], bf[8][2];
#pragma unroll
            for (int mi = 0; mi < 2; mi++) {
                const uint32_t* p = a_s + (wm * 32 + mi * 16 + lr) * SLD + kk * 8 + lc;
                af[mi][0] = p[0];
                af[mi][2] = p[4];
                af[mi][1] = p[8 * SLD];
                af[mi][3] = p[8 * SLD + 4];
            }
#pragma unroll
            for (int ni = 0; ni < 8; ni++) {
                const uint32_t* p = b_s + (wn * 64 + ni * 8 + lr) * SLD + kk * 8 + lc;
                bf[ni][0] = p[0];
                bf[ni][1] = p[4];
            }
#pragma unroll
            for (int mi = 0; mi < 2; mi++)
#pragma unroll
                for (int ni = 0; ni < 8; ni++) {
                    asm volatile(
                        "mma.sync.aligned.m16n8k8.row.col.f32.tf32.tf32.f32 "
                        "{%0,%1,%2,%3}, {%4,%5,%6,%7}, {%8,%9}, {%0,%1,%2,%3};"
                        : "+f"(acc[mi][ni][0]), "+f"(acc[mi][ni][1]),
                          "+f"(acc[mi][ni][2]), "+f"(acc[mi][ni][3])
                        : "r"(af[mi][0]), "r"(af[mi][1]), "r"(af[mi][2]), "r"(af[mi][3]),
                          "r"(bf[ni][0]), "r"(bf[ni][1]));
                }
        }
        __syncthreads();
    }

    // ---------------- fused epilogue ----------------
    const float INF = __int_as_float(0x7f800000);
    float rmin[2][2];

#pragma unroll
    for (int mi = 0; mi < 2; mi++)
#pragma unroll
        for (int h = 0; h < 2; h++) {
            int rloc = wm * 32 + mi * 16 + lr + 8 * h;
            float rm = INF;
#pragma unroll
            for (int ni = 0; ni < 8; ni++)
#pragma unroll
                for (int cc = 0; cc < 2; cc++) {
                    int cloc = wn * 64 + ni * 8 + lc * 2 + cc;
                    float e = 0.5f * c2s[cloc] - acc[mi][ni][h * 2 + cc];
                    int cg = n0 + cloc;
                    bool excl = (cg >= NCLS);
                    if (SELF) {
                        excl = excl || (cg == m0 + rloc);
                    } else if (cg == labs[rloc]) {
                        g_pos[m0 + rloc] = e;
                        excl = true;
                    }
                    if (!excl) rm = fminf(rm, e);
                }
            rmin[mi][h] = rm;
        }

    // reduce across the 4 lanes of each quad (they cover the 8 cols of each n8 tile)
#pragma unroll
    for (int mi = 0; mi < 2; mi++)
#pragma unroll
        for (int h = 0; h < 2; h++) {
            float v = rmin[mi][h];
            v = fminf(v, __shfl_xor_sync(0xffffffffu, v, 1));
            v = fminf(v, __shfl_xor_sync(0xffffffffu, v, 2));
            rmin[mi][h] = v;
        }

    if (lc == 0) {
#pragma unroll
        for (int mi = 0; mi < 2; mi++)
#pragma unroll
            for (int h = 0; h < 2; h++) {
                int rloc = wm * 32 + mi * 16 + lr + 8 * h;
                red[rloc * 2 + wn] = rmin[mi][h];
            }
    }
    __syncthreads();

    if (tid < 128) {
        float v = fminf(red[tid * 2], red[tid * 2 + 1]);
        int rg = m0 + tid;
        if (SELF) {
            if (rg < NCLS) g_mincc[(size_t)rg * NT + bx] = v;
        } else {
            g_minxc[(size_t)rg * NT + bx] = v;
        }
    }
}

// ---------------------------------------------------------------------------
// Final deterministic reduction -> scalar loss
// ---------------------------------------------------------------------------
__global__ void final_kernel(const int* __restrict__ labels, float* __restrict__ out) {
    __shared__ float cen[NCLS];
    __shared__ float part[256];
    const float INF = __int_as_float(0x7f800000);
    int tid = threadIdx.x;

    for (int j = tid; j < NCLS; j += 256) {
        float m = INF;
#pragma unroll
        for (int i = 0; i < NT; i++) m = fminf(m, g_mincc[(size_t)j * NT + i]);
        cen[j] = 0.5f * g_c2[j] + m;
    }
    __syncthreads();

    float acc = 0.f;
    for (int b = tid; b < BATCH; b += 256) {
        float m = INF;
#pragma unroll
        for (int i = 0; i < NT; i++) m = fminf(m, g_minxc[(size_t)b * NT + i]);
        // 0.5*||x||^2 cancels in (pos + MARGIN - neg), so e-values suffice
        float t1 = g_pos[b] + 5.0f - m;
        float t2 = 7.0f - cen[labels[b]];
        acc += fmaxf(t1, 0.f) + fmaxf(t2, 0.f);
    }
    part[tid] = acc;
    __syncthreads();
    for (int off = 128; off > 0; off >>= 1) {
        if (tid < off) part[tid] += part[tid + off];
        __syncthreads();
    }
    if (tid == 0) out[0] = part[0] * (1.0f / (float)BATCH);
}

// ---------------------------------------------------------------------------
// Launch
// ---------------------------------------------------------------------------
extern "C" void kernel_launch(void* const* d_in, const int* in_sizes, int n_in,
                              void* d_out, int out_size) {
    const float* x       = (const float*)d_in[0];
    const int*   labels  = (const int*)d_in[1];
    const float* centers = (const float*)d_in[2];
    float* out = (float*)d_out;

    const int smem_bytes = (2 * BM * SLD + 2 * BN * SLD + 128 + 256 + 128) * 4;  // 75776
    cudaFuncSetAttribute(gemm_min_kernel<false>,
                         cudaFuncAttributeMaxDynamicSharedMemorySize, smem_bytes);
    cudaFuncSetAttribute(gemm_min_kernel<true>,
                         cudaFuncAttributeMaxDynamicSharedMemorySize, smem_bytes);

    // 1. tf32-round inputs
    int n4x = BATCH * KDIM / 4;
    prep_x_kernel<<<(n4x + 255) / 256, 256>>>(x, n4x);
    int n4c = NCLS * KDIM / 4;
    prep_c_kernel<<<(n4c + 255) / 256, 256>>>(centers, n4c);

    // 2. exact squared norms of centers
    c2_kernel<<<NCLS, 256>>>(centers);

    // 3. main GEMM: x vs centers (grid.x = n-tiles so same-M tiles are adjacent -> L2 reuse of A)
    gemm_min_kernel<false><<<dim3(NT, BATCH / BM), 256, smem_bytes>>>(labels);

    // 4. centers vs centers
    gemm_min_kernel<true><<<dim3(NT, NPAD / BM), 256, smem_bytes>>>(labels);

    // 5. deterministic reduction to the scalar loss
    final_kernel<<<1, 256>>>(labels, out);
}

// round 5
// speedup vs baseline: 1.8710x; 1.8710x over previous
#include <cuda_runtime.h>
#include <cuda_fp16.h>
#include <cstdint>

// Problem constants
#define BATCH   16384
#define NCLS    1000
#define NPAD    1024
#define KDIM    1024

// GEMM tiling (fp16, same shape as proven round-1 tf32 kernel)
#define BM 128
#define BN 128
#define BKH 64               // halves per k-chunk (= 32 half2 = 128 bytes per row)
#define KT (KDIM / BKH)      // 16 k-chunks
#define NT 8                 // 8 * 128 = 1024 >= 1000
#define SLD 36               // smem row stride in uint32 (32 data + 4 pad, round-1 layout)

// ---------------------------------------------------------------------------
// Scratch (zero-initialized; pad rows of g_ch stay zero forever)
// ---------------------------------------------------------------------------
__device__ __half g_xh[(size_t)BATCH * KDIM];    // fp16 x
__device__ __half g_ch[(size_t)NPAD * KDIM];     // fp16 centers, rows 1000..1023 zero
__device__ float  g_c2[NPAD];                    // exact fp32 ||c||^2
__device__ float  g_pos[BATCH];
__device__ float  g_minxc[(size_t)BATCH * NT];
__device__ float  g_mincc[(size_t)NPAD * NT];
__device__ float  g_cen[NPAD];
__device__ float  g_part[64];

// ---------------------------------------------------------------------------
// Prep: fp32 -> fp16 (RN). NOTE: device symbols referenced IN device code —
// never passed from host (that was the rounds-3/4 bug: garbage host-side
// symbol address -> zero buffers -> rel_err 0.435).
// ---------------------------------------------------------------------------
__device__ __forceinline__ uint2 cvt4(float4 v) {
    __half2 lo = __floats2half2_rn(v.x, v.y);
    __half2 hi = __floats2half2_rn(v.z, v.w);
    uint2 o;
    o.x = *reinterpret_cast<uint32_t*>(&lo);
    o.y = *reinterpret_cast<uint32_t*>(&hi);
    return o;
}

__global__ void conv_x_kernel(const float* __restrict__ src, int n4) {
    int i = blockIdx.x * blockDim.x + threadIdx.x;
    if (i < n4)
        reinterpret_cast<uint2*>(g_xh)[i] = cvt4(reinterpret_cast<const float4*>(src)[i]);
}

__global__ void conv_c_kernel(const float* __restrict__ src, int n4) {
    int i = blockIdx.x * blockDim.x + threadIdx.x;
    if (i < n4)
        reinterpret_cast<uint2*>(g_ch)[i] = cvt4(reinterpret_cast<const float4*>(src)[i]);
}

// Exact fp32 squared norms of centers
__global__ void c2_kernel(const float* __restrict__ centers) {
    int j = blockIdx.x;
    const float* row = centers + (size_t)j * KDIM;
    float acc = 0.f;
    for (int k = threadIdx.x; k < KDIM; k += 256) {
        float v = row[k];
        acc += v * v;
    }
    __shared__ float s[256];
    s[threadIdx.x] = acc;
    __syncthreads();
    for (int off = 128; off > 0; off >>= 1) {
        if (threadIdx.x < off) s[threadIdx.x] += s[threadIdx.x + off];
        __syncthreads();
    }
    if (threadIdx.x == 0) g_c2[j] = s[0];
}

// ---------------------------------------------------------------------------
// fp16 GEMM + fused min epilogue (round-1 structure, half2 data units)
// e[r,c] = 0.5*||c_c||^2 - dot(A_r, C_c)
// SELF=false: A = g_xh; exclude c == label[r]; write g_pos, g_minxc
// SELF=true:  A = g_ch; exclude c == r;        write g_mincc
// ---------------------------------------------------------------------------
__device__ __forceinline__ void cp_tile(const __half* gbase, uint32_t* sbase, int tid) {
#pragma unroll
    for (int i = 0; i < 4; i++) {
        int g = i * 256 + tid;          // 0..1023 chunk id
        int r = g >> 3;                 // row 0..127
        int q = g & 7;                  // 16B chunk within row
        uint32_t d = (uint32_t)__cvta_generic_to_shared(sbase + r * SLD + q * 4);
        const __half* s = gbase + (size_t)r * KDIM + q * 8;
        asm volatile("cp.async.cg.shared.global [%0], [%1], 16;" :: "r"(d), "l"(s));
    }
}

template <bool SELF>
__global__ void __launch_bounds__(256)
gemm_min_kernel(const int* __restrict__ labels) {
    extern __shared__ uint32_t smem[];
    uint32_t* As  = smem;                       // 2 * 128 * 36 u32
    uint32_t* Bs  = smem + 2 * BM * SLD;        // 2 * 128 * 36 u32
    float*    c2s = (float*)(Bs + 2 * BN * SLD);  // 128 floats (pre-scaled by 0.5)
    float*    red = c2s + 128;                  // 128 * 2 floats
    int*      labs = (int*)(red + 256);         // 128 ints

    const int tid  = threadIdx.x;
    const int warp = tid >> 5;
    const int lane = tid & 31;
    const int wm   = warp >> 1;   // 0..3  (M warps, 32 rows each)
    const int wn   = warp & 1;    // 0..1  (N warps, 64 cols each)
    const int bx   = blockIdx.x;  // n-tile 0..7
    const int m0   = blockIdx.y * BM;
    const int n0   = bx * BN;

    const __half* A = SELF ? g_ch : g_xh;

    if (tid < 128) {
        c2s[tid] = 0.5f * g_c2[n0 + tid];
        if (!SELF) labs[tid] = labels[m0 + tid];
    }

    float acc[2][8][4];
#pragma unroll
    for (int mi = 0; mi < 2; mi++)
#pragma unroll
        for (int ni = 0; ni < 8; ni++)
#pragma unroll
            for (int r = 0; r < 4; r++) acc[mi][ni][r] = 0.f;

    const __half* Abase = A + (size_t)m0 * KDIM;
    const __half* Bbase = g_ch + (size_t)n0 * KDIM;

    // prologue: stage 0
    cp_tile(Abase, As, tid);
    cp_tile(Bbase, Bs, tid);
    asm volatile("cp.async.commit_group;");

    const int lr = lane >> 2, lc = lane & 3;

    for (int kt = 0; kt < KT; kt++) {
        if (kt + 1 < KT) {
            int st = (kt + 1) & 1;
            cp_tile(Abase + (size_t)(kt + 1) * BKH, As + st * BM * SLD, tid);
            cp_tile(Bbase + (size_t)(kt + 1) * BKH, Bs + st * BN * SLD, tid);
            asm volatile("cp.async.commit_group;");
            asm volatile("cp.async.wait_group 1;");
        } else {
            asm volatile("cp.async.wait_group 0;");
        }
        __syncthreads();

        const uint32_t* a_s = As + (kt & 1) * BM * SLD;
        const uint32_t* b_s = Bs + (kt & 1) * BN * SLD;

#pragma unroll
        for (int kk = 0; kk < 4; kk++) {
            // identical indexing to the proven round-1 kernel; elements are half2
            uint32_t af[2][4], bf[8][2];
#pragma unroll
            for (int mi = 0; mi < 2; mi++) {
                const uint32_t* p = a_s + (wm * 32 + mi * 16 + lr) * SLD + kk * 8 + lc;
                af[mi][0] = p[0];            // a0: (row lr,    k 2lc..2lc+1)
                af[mi][2] = p[4];            // a2: (row lr,    k 2lc+8..9)
                af[mi][1] = p[8 * SLD];      // a1: (row lr+8,  k 2lc..2lc+1)
                af[mi][3] = p[8 * SLD + 4];  // a3: (row lr+8,  k 2lc+8..9)
            }
#pragma unroll
            for (int ni = 0; ni < 8; ni++) {
                const uint32_t* p = b_s + (wn * 64 + ni * 8 + lr) * SLD + kk * 8 + lc;
                bf[ni][0] = p[0];            // b0: (k 2lc..2lc+1, n lr)
                bf[ni][1] = p[4];            // b1: (k 2lc+8..9,   n lr)
            }
#pragma unroll
            for (int mi = 0; mi < 2; mi++)
#pragma unroll
                for (int ni = 0; ni < 8; ni++) {
                    asm volatile(
                        "mma.sync.aligned.m16n8k16.row.col.f32.f16.f16.f32 "
                        "{%0,%1,%2,%3}, {%4,%5,%6,%7}, {%8,%9}, {%0,%1,%2,%3};"
                        : "+f"(acc[mi][ni][0]), "+f"(acc[mi][ni][1]),
                          "+f"(acc[mi][ni][2]), "+f"(acc[mi][ni][3])
                        : "r"(af[mi][0]), "r"(af[mi][1]), "r"(af[mi][2]), "r"(af[mi][3]),
                          "r"(bf[ni][0]), "r"(bf[ni][1]));
                }
        }
        __syncthreads();
    }

    // ---------------- fused epilogue (verbatim round 1) ----------------
    const float INF = __int_as_float(0x7f800000);
    float rmin[2][2];

#pragma unroll
    for (int mi = 0; mi < 2; mi++)
#pragma unroll
        for (int h = 0; h < 2; h++) {
            int rloc = wm * 32 + mi * 16 + lr + 8 * h;
            float rm = INF;
#pragma unroll
            for (int ni = 0; ni < 8; ni++)
#pragma unroll
                for (int cc = 0; cc < 2; cc++) {
                    int cloc = wn * 64 + ni * 8 + lc * 2 + cc;
                    float e = c2s[cloc] - acc[mi][ni][h * 2 + cc];
                    int cg = n0 + cloc;
                    bool excl = (cg >= NCLS);
                    if (SELF) {
                        excl = excl || (cg == m0 + rloc);
                    } else if (cg == labs[rloc]) {
                        g_pos[m0 + rloc] = e;
                        excl = true;
                    }
                    if (!excl) rm = fminf(rm, e);
                }
            rmin[mi][h] = rm;
        }

#pragma unroll
    for (int mi = 0; mi < 2; mi++)
#pragma unroll
        for (int h = 0; h < 2; h++) {
            float v = rmin[mi][h];
            v = fminf(v, __shfl_xor_sync(0xffffffffu, v, 1));
            v = fminf(v, __shfl_xor_sync(0xffffffffu, v, 2));
            rmin[mi][h] = v;
        }

    if (lc == 0) {
#pragma unroll
        for (int mi = 0; mi < 2; mi++)
#pragma unroll
            for (int h = 0; h < 2; h++) {
                int rloc = wm * 32 + mi * 16 + lr + 8 * h;
                red[rloc * 2 + wn] = rmin[mi][h];
            }
    }
    __syncthreads();

    if (tid < 128) {
        float v = fminf(red[tid * 2], red[tid * 2 + 1]);
        int rg = m0 + tid;
        if (SELF) {
            if (rg < NCLS) g_mincc[(size_t)rg * NT + bx] = v;
        } else {
            g_minxc[(size_t)rg * NT + bx] = v;
        }
    }
}

// ---------------------------------------------------------------------------
// Deterministic reduction chain
// ---------------------------------------------------------------------------
__global__ void cen_kernel() {
    int j = blockIdx.x * blockDim.x + threadIdx.x;
    if (j < NCLS) {
        float4 a = reinterpret_cast<const float4*>(g_mincc)[j * 2];
        float4 b = reinterpret_cast<const float4*>(g_mincc)[j * 2 + 1];
        float m = fminf(fminf(fminf(a.x, a.y), fminf(a.z, a.w)),
                        fminf(fminf(b.x, b.y), fminf(b.z, b.w)));
        g_cen[j] = 0.5f * g_c2[j] + m;
    }
}

__global__ void partial_kernel(const int* __restrict__ labels) {
    int b = blockIdx.x * 256 + threadIdx.x;
    float4 a = reinterpret_cast<const float4*>(g_minxc)[b * 2];
    float4 c = reinterpret_cast<const float4*>(g_minxc)[b * 2 + 1];
    float m = fminf(fminf(fminf(a.x, a.y), fminf(a.z, a.w)),
                    fminf(fminf(c.x, c.y), fminf(c.z, c.w)));
    float t1 = g_pos[b] + 5.0f - m;     // 0.5||x||^2 cancels in pos - neg
    float t2 = 7.0f - g_cen[labels[b]];
    float v = fmaxf(t1, 0.f) + fmaxf(t2, 0.f);
    __shared__ float s[256];
    s[threadIdx.x] = v;
    __syncthreads();
    for (int off = 128; off > 0; off >>= 1) {
        if (threadIdx.x < off) s[threadIdx.x] += s[threadIdx.x + off];
        __syncthreads();
    }
    if (threadIdx.x == 0) g_part[blockIdx.x] = s[0];
}

__global__ void finish_kernel(float* __restrict__ out) {
    int t = threadIdx.x;   // 32 threads
    float v = g_part[t] + g_part[t + 32];
#pragma unroll
    for (int off = 16; off > 0; off >>= 1)
        v += __shfl_xor_sync(0xffffffffu, v, off);
    if (t == 0) out[0] = v * (1.0f / (float)BATCH);
}

// ---------------------------------------------------------------------------
// Launch
// ---------------------------------------------------------------------------
extern "C" void kernel_launch(void* const* d_in, const int* in_sizes, int n_in,
                              void* d_out, int out_size) {
    const float* x       = (const float*)d_in[0];
    const int*   labels  = (const int*)d_in[1];
    const float* centers = (const float*)d_in[2];
    float* out = (float*)d_out;

    const int smem_bytes = (2 * BM * SLD + 2 * BN * SLD + 128 + 256 + 128) * 4;  // 75776
    cudaFuncSetAttribute(gemm_min_kernel<false>,
                         cudaFuncAttributeMaxDynamicSharedMemorySize, smem_bytes);
    cudaFuncSetAttribute(gemm_min_kernel<true>,
                         cudaFuncAttributeMaxDynamicSharedMemorySize, smem_bytes);

    // fp16 conversions + exact center norms (device symbols written in device code)
    int n4x = BATCH * KDIM / 4;
    conv_x_kernel<<<n4x / 256, 256>>>(x, n4x);
    int n4c = NCLS * KDIM / 4;
    conv_c_kernel<<<(n4c + 255) / 256, 256>>>(centers, n4c);
    c2_kernel<<<NCLS, 256>>>(centers);

    // main GEMM: x vs centers
    gemm_min_kernel<false><<<dim3(NT, BATCH / BM), 256, smem_bytes>>>(labels);

    // centers vs centers
    gemm_min_kernel<true><<<dim3(NT, NPAD / BM), 256, smem_bytes>>>(labels);

    // reduction chain
    cen_kernel<<<4, 256>>>();
    partial_kernel<<<64, 256>>>(labels);
    finish_kernel<<<1, 32>>>(out);
}